// round 8
// baseline (speedup 1.0000x reference)
#include <cuda_runtime.h>
#include <cuda_fp16.h>

typedef unsigned int u32;

#define NT  256
#define BM  128
#define BN  64
#define Dh  128
#define SEQ 2048
#define NIT (SEQ / BN)
#define LOG2E 1.44269504088896340736f

// ---- smem byte layout ----
#define QH_OFF 0
#define QL_OFF 32768
#define K_OFF  65536          // + buf*32768 ; lo at +16384
#define V_OFF  131072         // + buf*16384 (hi only)
#define SMEM_BYTES 163840

static __device__ __forceinline__ u32 cvta_smem(const void* p) {
    u32 a;
    asm("{ .reg .u64 t; cvta.to.shared.u64 t, %1; cvt.u32.u64 %0, t; }" : "=r"(a) : "l"(p));
    return a;
}
static __device__ __forceinline__ u32 swoff(int row, int ch) {
    return (u32)(row * 256 + ((ch ^ (row & 7)) << 4));
}
// fast 2^t for t <= 0 on FMA/ALU pipes (Cephes quintic, rel err ~2e-7)
static __device__ __forceinline__ float fex2(float t) {
    t = fmaxf(t, -28.0f);
    float fi = floorf(t);
    float f  = t - fi;
    int   i  = (int)fi;
    float p = 1.3333558e-3f;
    p = fmaf(p, f, 9.6181291e-3f);
    p = fmaf(p, f, 5.5504109e-2f);
    p = fmaf(p, f, 2.4022648e-1f);
    p = fmaf(p, f, 6.9314720e-1f);
    p = fmaf(p, f, 1.0f);
    return __int_as_float(__float_as_int(p) + (i << 23));
}
static __device__ __forceinline__ u32 pack2(float x0, float x1) {
    __half2 h = __floats2half2_rn(x0, x1);
    return *(u32*)&h;
}
static __device__ __forceinline__ void split2(float x0, float x1, u32& hi, u32& lo) {
    __half2 h = __floats2half2_rn(x0, x1);
    float2  b = __half22float2(h);
    __half2 l = __floats2half2_rn(x0 - b.x, x1 - b.y);
    hi = *(u32*)&h; lo = *(u32*)&l;
}

static __device__ __forceinline__ void ldm4(u32 addr, u32& r0, u32& r1, u32& r2, u32& r3) {
    asm volatile("ldmatrix.sync.aligned.m8n8.x4.shared.b16 {%0,%1,%2,%3}, [%4];"
                 : "=r"(r0), "=r"(r1), "=r"(r2), "=r"(r3) : "r"(addr));
}
static __device__ __forceinline__ void ldm4t(u32 addr, u32& r0, u32& r1, u32& r2, u32& r3) {
    asm volatile("ldmatrix.sync.aligned.m8n8.x4.trans.shared.b16 {%0,%1,%2,%3}, [%4];"
                 : "=r"(r0), "=r"(r1), "=r"(r2), "=r"(r3) : "r"(addr));
}
static __device__ __forceinline__ void mma(float* d, u32 a0, u32 a1, u32 a2, u32 a3, u32 b0, u32 b1) {
    asm volatile("mma.sync.aligned.m16n8k16.row.col.f32.f16.f16.f32 "
                 "{%0,%1,%2,%3}, {%4,%5,%6,%7}, {%8,%9}, {%0,%1,%2,%3};"
                 : "+f"(d[0]), "+f"(d[1]), "+f"(d[2]), "+f"(d[3])
                 : "r"(a0), "r"(a1), "r"(a2), "r"(a3), "r"(b0), "r"(b1));
}

static __device__ __forceinline__ void conv_k(const float* __restrict__ src,
                                              char* dh, char* dl, int tid) {
    #pragma unroll
    for (int p = 0; p < 4; p++) {
        int idx = tid + p * 256;
        int row = idx >> 4, ch = idx & 15;
        const float* s = src + (size_t)row * Dh + ch * 8;
        float4 a = *(const float4*)s;
        float4 b = *(const float4*)(s + 4);
        u32 h0, l0, h1, l1, h2, l2, h3, l3;
        split2(a.x, a.y, h0, l0); split2(a.z, a.w, h1, l1);
        split2(b.x, b.y, h2, l2); split2(b.z, b.w, h3, l3);
        u32 off = swoff(row, ch);
        *(uint4*)(dh + off) = make_uint4(h0, h1, h2, h3);
        *(uint4*)(dl + off) = make_uint4(l0, l1, l2, l3);
    }
}
static __device__ __forceinline__ void conv_v(const float* __restrict__ src,
                                              char* dh, int tid) {
    #pragma unroll
    for (int p = 0; p < 4; p++) {
        int idx = tid + p * 256;
        int row = idx >> 4, ch = idx & 15;
        const float* s = src + (size_t)row * Dh + ch * 8;
        float4 a = *(const float4*)s;
        float4 b = *(const float4*)(s + 4);
        u32 off = swoff(row, ch);
        *(uint4*)(dh + off) = make_uint4(pack2(a.x, a.y), pack2(a.z, a.w),
                                         pack2(b.x, b.y), pack2(b.z, b.w));
    }
}

__global__ __launch_bounds__(NT, 1)
void attn_hmma(const float* __restrict__ qg, const float* __restrict__ kg,
               const float* __restrict__ vg, const float* __restrict__ scg,
               float* __restrict__ og)
{
    extern __shared__ char sm[];
    const u32 smb = cvta_smem(sm);
    const int tid = threadIdx.x, lane = tid & 31, wid = tid >> 5;

    const int tile = blockIdx.x;
    const int bh   = blockIdx.y;
    const size_t base = (size_t)bh * SEQ * Dh;
    const float* Qg = qg + base + (size_t)tile * BM * Dh;
    const float* Kg = kg + base;
    const float* Vg = vg + base;
    float*       Og = og + base + (size_t)tile * BM * Dh;
    const float scL = scg[bh] * LOG2E;

    // ---- prologue: Q (scale folded, split) + tile 0 ----
    #pragma unroll
    for (int p = 0; p < 8; p++) {
        int idx = tid + p * 256;
        int row = idx >> 4, ch = idx & 15;
        const float* s = Qg + (size_t)row * Dh + ch * 8;
        float4 a = *(const float4*)s;
        float4 b = *(const float4*)(s + 4);
        u32 h0, l0, h1, l1, h2, l2, h3, l3;
        split2(a.x * scL, a.y * scL, h0, l0); split2(a.z * scL, a.w * scL, h1, l1);
        split2(b.x * scL, b.y * scL, h2, l2); split2(b.z * scL, b.w * scL, h3, l3);
        u32 off = swoff(row, ch);
        *(uint4*)(sm + QH_OFF + off) = make_uint4(h0, h1, h2, h3);
        *(uint4*)(sm + QL_OFF + off) = make_uint4(l0, l1, l2, l3);
    }
    conv_k(Kg, sm + K_OFF, sm + K_OFF + 16384, tid);
    conv_v(Vg, sm + V_OFF, tid);
    __syncthreads();

    // ---- per-warp state ----
    float oacc[16][4];
    #pragma unroll
    for (int f = 0; f < 16; f++)
        #pragma unroll
        for (int j = 0; j < 4; j++) oacc[f][j] = 0.f;
    float mA = -1e30f, mB = -1e30f, lA = 0.f, lB = 0.f;   // lA/lB: lane-partial

    const int wr0 = wid * 16;
    const int qrow = wr0 + (lane & 15);
    const int qchh = lane >> 4;
    const int kn   = (lane & 7) + ((lane >> 4) << 3);
    const int kchh = (lane >> 3) & 1;
    const int vkey = (lane & 7) + (((lane >> 3) & 1) << 3);
    const int vchh = lane >> 4;

    #pragma unroll 1
    for (int n = 0; n < NIT; n++) {
        const int buf = n & 1;
        const u32 khb = smb + K_OFF + buf * 32768;
        const u32 klb = khb + 16384;
        const u32 vhb = smb + V_OFF + buf * 16384;

        // ---- S = (Qh+Ql)(Kh+Kl)^T, 3 products ----
        float sacc[8][4];
        #pragma unroll
        for (int f = 0; f < 8; f++)
            #pragma unroll
            for (int j = 0; j < 4; j++) sacc[f][j] = 0.f;

        #pragma unroll
        for (int kk = 0; kk < 8; kk++) {
            u32 qoff = swoff(qrow, kk * 2 + qchh);
            u32 qh0, qh1, qh2, qh3, ql0, ql1, ql2, ql3;
            ldm4(smb + QH_OFF + qoff, qh0, qh1, qh2, qh3);
            ldm4(smb + QL_OFF + qoff, ql0, ql1, ql2, ql3);
            #pragma unroll
            for (int jp = 0; jp < 4; jp++) {
                u32 koff = swoff(jp * 16 + kn, kk * 2 + kchh);
                u32 kb0, kb1, kb2, kb3, lb0, lb1, lb2, lb3;
                ldm4(khb + koff, kb0, kb1, kb2, kb3);
                ldm4(klb + koff, lb0, lb1, lb2, lb3);
                mma(sacc[jp * 2],     qh0, qh1, qh2, qh3, kb0, kb1);
                mma(sacc[jp * 2],     qh0, qh1, qh2, qh3, lb0, lb1);
                mma(sacc[jp * 2],     ql0, ql1, ql2, ql3, kb0, kb1);
                mma(sacc[jp * 2 + 1], qh0, qh1, qh2, qh3, kb2, kb3);
                mma(sacc[jp * 2 + 1], qh0, qh1, qh2, qh3, lb2, lb3);
                mma(sacc[jp * 2 + 1], ql0, ql1, ql2, ql3, kb2, kb3);
            }
        }

        // ---- online softmax (log2 domain, poly exp, deferred l-reduction) ----
        float rmaxA = -1e30f, rmaxB = -1e30f;
        #pragma unroll
        for (int f = 0; f < 8; f++) {
            rmaxA = fmaxf(rmaxA, fmaxf(sacc[f][0], sacc[f][1]));
            rmaxB = fmaxf(rmaxB, fmaxf(sacc[f][2], sacc[f][3]));
        }
        rmaxA = fmaxf(rmaxA, __shfl_xor_sync(0xffffffffu, rmaxA, 1));
        rmaxA = fmaxf(rmaxA, __shfl_xor_sync(0xffffffffu, rmaxA, 2));
        rmaxB = fmaxf(rmaxB, __shfl_xor_sync(0xffffffffu, rmaxB, 1));
        rmaxB = fmaxf(rmaxB, __shfl_xor_sync(0xffffffffu, rmaxB, 2));

        float mnA = fmaxf(mA, rmaxA), mnB = fmaxf(mB, rmaxB);
        float aA = fex2(mA - mnA), aB = fex2(mB - mnB);
        mA = mnA; mB = mnB;

        u32 ph[4][4];
        float sA = 0.f, sB = 0.f;
        #pragma unroll
        for (int kk = 0; kk < 4; kk++) {
            float p0 = fex2(sacc[2 * kk][0] - mnA);
            float p1 = fex2(sacc[2 * kk][1] - mnA);
            float p2 = fex2(sacc[2 * kk][2] - mnB);
            float p3 = fex2(sacc[2 * kk][3] - mnB);
            float p4 = fex2(sacc[2 * kk + 1][0] - mnA);
            float p5 = fex2(sacc[2 * kk + 1][1] - mnA);
            float p6 = fex2(sacc[2 * kk + 1][2] - mnB);
            float p7 = fex2(sacc[2 * kk + 1][3] - mnB);
            sA += (p0 + p1) + (p4 + p5);
            sB += (p2 + p3) + (p6 + p7);
            ph[kk][0] = pack2(p0, p1);
            ph[kk][1] = pack2(p2, p3);
            ph[kk][2] = pack2(p4, p5);
            ph[kk][3] = pack2(p6, p7);
        }
        // lane-partial l (alpha is quad-uniform -> reduce once in epilogue)
        lA = fmaf(lA, aA, sA);
        lB = fmaf(lB, aB, sB);

        // skip O-rescale when no lane's max moved
        if (__any_sync(0xffffffffu, (aA < 1.f) | (aB < 1.f))) {
            #pragma unroll
            for (int f = 0; f < 16; f++) {
                oacc[f][0] *= aA; oacc[f][1] *= aA;
                oacc[f][2] *= aB; oacc[f][3] *= aB;
            }
        }

        // ---- O += Ph @ Vh ----
        #pragma unroll
        for (int kk = 0; kk < 4; kk++) {
            #pragma unroll
            for (int dp = 0; dp < 8; dp++) {
                u32 voff = swoff(kk * 16 + vkey, dp * 2 + vchh);
                u32 vb0, vb1, vb2, vb3;
                ldm4t(vhb + voff, vb0, vb1, vb2, vb3);
                mma(oacc[2 * dp],     ph[kk][0], ph[kk][1], ph[kk][2], ph[kk][3], vb0, vb1);
                mma(oacc[2 * dp + 1], ph[kk][0], ph[kk][1], ph[kk][2], ph[kk][3], vb2, vb3);
            }
        }

        // ---- convert next tile (1 sync/iter) ----
        if (n + 1 < NIT) {
            conv_k(Kg + (size_t)(n + 1) * BN * Dh,
                   sm + K_OFF + (buf ^ 1) * 32768,
                   sm + K_OFF + (buf ^ 1) * 32768 + 16384, tid);
            conv_v(Vg + (size_t)(n + 1) * BN * Dh,
                   sm + V_OFF + (buf ^ 1) * 16384, tid);
        }
        __syncthreads();
    }

    // ---- epilogue: final l reduction over the quad, then store ----
    lA += __shfl_xor_sync(0xffffffffu, lA, 1);
    lA += __shfl_xor_sync(0xffffffffu, lA, 2);
    lB += __shfl_xor_sync(0xffffffffu, lB, 1);
    lB += __shfl_xor_sync(0xffffffffu, lB, 2);
    const float iA = 1.f / lA, iB = 1.f / lB;
    const int ra = wr0 + (lane >> 2);
    const int rb = ra + 8;
    const int cb = 2 * (lane & 3);
    #pragma unroll
    for (int f = 0; f < 16; f++) {
        float2 va; va.x = oacc[f][0] * iA; va.y = oacc[f][1] * iA;
        float2 vb; vb.x = oacc[f][2] * iB; vb.y = oacc[f][3] * iB;
        *(float2*)(Og + (size_t)ra * Dh + f * 8 + cb) = va;
        *(float2*)(Og + (size_t)rb * Dh + f * 8 + cb) = vb;
    }
}

extern "C" void kernel_launch(void* const* d_in, const int* in_sizes, int n_in,
                              void* d_out, int out_size)
{
    const float* q     = (const float*)d_in[0];
    const float* k     = (const float*)d_in[1];
    const float* v     = (const float*)d_in[2];
    const float* scale = (const float*)d_in[3];
    float* out = (float*)d_out;

    cudaFuncSetAttribute(attn_hmma, cudaFuncAttributeMaxDynamicSharedMemorySize, SMEM_BYTES);
    dim3 grid(SEQ / BM, 4 * 16);
    attn_hmma<<<grid, NT, SMEM_BYTES>>>(q, k, v, scale, out);
}

// round 9
// speedup vs baseline: 1.3483x; 1.3483x over previous
#include <cuda_runtime.h>
#include <cuda_fp16.h>

typedef unsigned int u32;

#define NT  256
#define BM  128
#define BN  64
#define Dh  128
#define SEQ 2048
#define NIT (SEQ / BN)
#define NBH 64
#define LOG2E 1.44269504088896340736f

// ---- smem byte layout (main kernel) ----
#define QH_OFF 0
#define QL_OFF 32768
#define K_OFF  65536          // + buf*32768 ; lo at +16384
#define V_OFF  131072         // + buf*16384 (hi only)
#define SMEM_BYTES 163840

// ---- global scratch: pre-split f16 images in exact swizzled smem layout ----
__device__ u32 gQsc[NBH * 16 * 16384];   // per (bh,qtile): 32KB hi + 32KB lo
__device__ u32 gKsc[NBH * 32 * 8192];    // per (bh,ktile): 16KB hi + 16KB lo
__device__ u32 gVsc[NBH * 32 * 4096];    // per (bh,ktile): 16KB hi

static __device__ __forceinline__ u32 cvta_smem(const void* p) {
    u32 a;
    asm("{ .reg .u64 t; cvta.to.shared.u64 t, %1; cvt.u32.u64 %0, t; }" : "=r"(a) : "l"(p));
    return a;
}
static __device__ __forceinline__ u32 swoff(int row, int ch) {
    return (u32)(row * 256 + ((ch ^ (row & 7)) << 4));
}
static __device__ __forceinline__ float ex2(float x) {
    float y; asm("ex2.approx.f32 %0, %1;" : "=f"(y) : "f"(x)); return y;
}
static __device__ __forceinline__ u32 pack2(float x0, float x1) {
    __half2 h = __floats2half2_rn(x0, x1);
    return *(u32*)&h;
}
static __device__ __forceinline__ void split2(float x0, float x1, u32& hi, u32& lo) {
    __half2 h = __floats2half2_rn(x0, x1);
    float2  b = __half22float2(h);
    __half2 l = __floats2half2_rn(x0 - b.x, x1 - b.y);
    hi = *(u32*)&h; lo = *(u32*)&l;
}

static __device__ __forceinline__ void ldm4(u32 addr, u32& r0, u32& r1, u32& r2, u32& r3) {
    asm volatile("ldmatrix.sync.aligned.m8n8.x4.shared.b16 {%0,%1,%2,%3}, [%4];"
                 : "=r"(r0), "=r"(r1), "=r"(r2), "=r"(r3) : "r"(addr));
}
static __device__ __forceinline__ void ldm4t(u32 addr, u32& r0, u32& r1, u32& r2, u32& r3) {
    asm volatile("ldmatrix.sync.aligned.m8n8.x4.trans.shared.b16 {%0,%1,%2,%3}, [%4];"
                 : "=r"(r0), "=r"(r1), "=r"(r2), "=r"(r3) : "r"(addr));
}
static __device__ __forceinline__ void mma(float* d, u32 a0, u32 a1, u32 a2, u32 a3, u32 b0, u32 b1) {
    asm volatile("mma.sync.aligned.m16n8k16.row.col.f32.f16.f16.f32 "
                 "{%0,%1,%2,%3}, {%4,%5,%6,%7}, {%8,%9}, {%0,%1,%2,%3};"
                 : "+f"(d[0]), "+f"(d[1]), "+f"(d[2]), "+f"(d[3])
                 : "r"(a0), "r"(a1), "r"(a2), "r"(a3), "r"(b0), "r"(b1));
}
#define CP16(dst, src) \
    asm volatile("cp.async.cg.shared.global [%0], [%1], 16;" :: "r"(dst), "l"(src))
#define CP_COMMIT() asm volatile("cp.async.commit_group;" ::: "memory")
#define CP_WAIT0()  asm volatile("cp.async.wait_group 0;"  ::: "memory")

// ============ prep kernel: split f32 -> f16 hi/lo swizzled images ============
__global__ __launch_bounds__(NT, 4)
void prep_kernel(const float* __restrict__ qg, const float* __restrict__ kg,
                 const float* __restrict__ vg, const float* __restrict__ scg)
{
    const int t = blockIdx.x;        // 0..31 (64-row slab)
    const int bh = blockIdx.y;       // 0..63
    const int tid = threadIdx.x;
    const size_t base = (size_t)bh * SEQ * Dh + (size_t)t * 64 * Dh;
    const float scL = scg[bh] * LOG2E;

    // ---- K tile t: hi + lo ----
    {
        const float* src = kg + base;
        u32* dh = gKsc + (size_t)(bh * 32 + t) * 8192;
        u32* dl = dh + 4096;
        #pragma unroll
        for (int p = 0; p < 4; p++) {
            int idx = tid + p * 256;
            int row = idx >> 4, ch = idx & 15;
            const float* s = src + (size_t)row * Dh + ch * 8;
            float4 a = *(const float4*)s;
            float4 b = *(const float4*)(s + 4);
            u32 h0, l0, h1, l1, h2, l2, h3, l3;
            split2(a.x, a.y, h0, l0); split2(a.z, a.w, h1, l1);
            split2(b.x, b.y, h2, l2); split2(b.z, b.w, h3, l3);
            u32 off = swoff(row, ch) >> 2;
            *(uint4*)(dh + off) = make_uint4(h0, h1, h2, h3);
            *(uint4*)(dl + off) = make_uint4(l0, l1, l2, l3);
        }
    }
    // ---- V tile t: hi only ----
    {
        const float* src = vg + base;
        u32* dv = gVsc + (size_t)(bh * 32 + t) * 4096;
        #pragma unroll
        for (int p = 0; p < 4; p++) {
            int idx = tid + p * 256;
            int row = idx >> 4, ch = idx & 15;
            const float* s = src + (size_t)row * Dh + ch * 8;
            float4 a = *(const float4*)s;
            float4 b = *(const float4*)(s + 4);
            u32 off = swoff(row, ch) >> 2;
            *(uint4*)(dv + off) = make_uint4(pack2(a.x, a.y), pack2(a.z, a.w),
                                             pack2(b.x, b.y), pack2(b.z, b.w));
        }
    }
    // ---- Q rows [t*64, t*64+64): scale folded, hi + lo, qtile = t/2 ----
    {
        const float* src = qg + base;
        u32* dh = gQsc + (size_t)(bh * 16 + (t >> 1)) * 16384;
        u32* dl = dh + 8192;
        const int rbase = (t & 1) * 64;
        #pragma unroll
        for (int p = 0; p < 4; p++) {
            int idx = tid + p * 256;
            int row = idx >> 4, ch = idx & 15;
            const float* s = src + (size_t)row * Dh + ch * 8;
            float4 a = *(const float4*)s;
            float4 b = *(const float4*)(s + 4);
            u32 h0, l0, h1, l1, h2, l2, h3, l3;
            split2(a.x * scL, a.y * scL, h0, l0); split2(a.z * scL, a.w * scL, h1, l1);
            split2(b.x * scL, b.y * scL, h2, l2); split2(b.z * scL, b.w * scL, h3, l3);
            u32 off = swoff(rbase + row, ch) >> 2;
            *(uint4*)(dh + off) = make_uint4(h0, h1, h2, h3);
            *(uint4*)(dl + off) = make_uint4(l0, l1, l2, l3);
        }
    }
}

// ============ main kernel ============
__global__ __launch_bounds__(NT, 1)
void attn_hmma(float* __restrict__ og)
{
    extern __shared__ char sm[];
    const u32 smb = cvta_smem(sm);
    const int tid = threadIdx.x, lane = tid & 31, wid = tid >> 5;

    const int tile = blockIdx.x;
    const int bh   = blockIdx.y;
    float* Og = og + (size_t)bh * SEQ * Dh + (size_t)tile * BM * Dh;

    const char* gQ = (const char*)(gQsc + (size_t)(bh * 16 + tile) * 16384);
    const char* gK = (const char*)(gKsc + (size_t)(bh * 32) * 8192);
    const char* gV = (const char*)(gVsc + (size_t)(bh * 32) * 4096);

    // ---- prologue: async copy Q (64KB) + K/V tile 0 ----
    #pragma unroll
    for (int i = 0; i < 16; i++)
        CP16(smb + QH_OFF + tid * 16 + i * 4096, gQ + tid * 16 + i * 4096);
    #pragma unroll
    for (int i = 0; i < 8; i++)
        CP16(smb + K_OFF + tid * 16 + i * 4096, gK + tid * 16 + i * 4096);
    #pragma unroll
    for (int i = 0; i < 4; i++)
        CP16(smb + V_OFF + tid * 16 + i * 4096, gV + tid * 16 + i * 4096);
    CP_COMMIT();
    CP_WAIT0();
    __syncthreads();

    // ---- per-warp state ----
    float oacc[16][4];
    #pragma unroll
    for (int f = 0; f < 16; f++)
        #pragma unroll
        for (int j = 0; j < 4; j++) oacc[f][j] = 0.f;
    float mA = -1e30f, mB = -1e30f, lA = 0.f, lB = 0.f;   // l: lane-partial

    const int wr0 = wid * 16;
    const int qrow = wr0 + (lane & 15);
    const int qchh = lane >> 4;
    const int kn   = (lane & 7) + ((lane >> 4) << 3);
    const int kchh = (lane >> 3) & 1;
    const int vkey = (lane & 7) + (((lane >> 3) & 1) << 3);
    const int vchh = lane >> 4;

    #pragma unroll 1
    for (int n = 0; n < NIT; n++) {
        const int buf = n & 1;
        const u32 khb = smb + K_OFF + buf * 32768;
        const u32 klb = khb + 16384;
        const u32 vhb = smb + V_OFF + buf * 16384;

        // ---- issue async copies for tile n+1 (overlap with compute) ----
        if (n + 1 < NIT) {
            const char* nk = gK + (size_t)(n + 1) * 32768;
            const char* nv = gV + (size_t)(n + 1) * 16384;
            u32 kd = smb + K_OFF + (buf ^ 1) * 32768 + tid * 16;
            u32 vd = smb + V_OFF + (buf ^ 1) * 16384 + tid * 16;
            #pragma unroll
            for (int i = 0; i < 8; i++)
                CP16(kd + i * 4096, nk + tid * 16 + i * 4096);
            #pragma unroll
            for (int i = 0; i < 4; i++)
                CP16(vd + i * 4096, nv + tid * 16 + i * 4096);
            CP_COMMIT();
        }

        // ---- S = (Qh+Ql)(Kh+Kl)^T, 3 products ----
        float sacc[8][4];
        #pragma unroll
        for (int f = 0; f < 8; f++)
            #pragma unroll
            for (int j = 0; j < 4; j++) sacc[f][j] = 0.f;

        #pragma unroll
        for (int kk = 0; kk < 8; kk++) {
            u32 qoff = swoff(qrow, kk * 2 + qchh);
            u32 qh0, qh1, qh2, qh3, ql0, ql1, ql2, ql3;
            ldm4(smb + QH_OFF + qoff, qh0, qh1, qh2, qh3);
            ldm4(smb + QL_OFF + qoff, ql0, ql1, ql2, ql3);
            #pragma unroll
            for (int jp = 0; jp < 4; jp++) {
                u32 koff = swoff(jp * 16 + kn, kk * 2 + kchh);
                u32 kb0, kb1, kb2, kb3, lb0, lb1, lb2, lb3;
                ldm4(khb + koff, kb0, kb1, kb2, kb3);
                ldm4(klb + koff, lb0, lb1, lb2, lb3);
                mma(sacc[jp * 2],     qh0, qh1, qh2, qh3, kb0, kb1);
                mma(sacc[jp * 2],     qh0, qh1, qh2, qh3, lb0, lb1);
                mma(sacc[jp * 2],     ql0, ql1, ql2, ql3, kb0, kb1);
                mma(sacc[jp * 2 + 1], qh0, qh1, qh2, qh3, kb2, kb3);
                mma(sacc[jp * 2 + 1], qh0, qh1, qh2, qh3, lb2, lb3);
                mma(sacc[jp * 2 + 1], ql0, ql1, ql2, ql3, kb2, kb3);
            }
        }

        // ---- online softmax (log2 domain, MUFU ex2) ----
        float rmaxA = -1e30f, rmaxB = -1e30f;
        #pragma unroll
        for (int f = 0; f < 8; f++) {
            rmaxA = fmaxf(rmaxA, fmaxf(sacc[f][0], sacc[f][1]));
            rmaxB = fmaxf(rmaxB, fmaxf(sacc[f][2], sacc[f][3]));
        }
        rmaxA = fmaxf(rmaxA, __shfl_xor_sync(0xffffffffu, rmaxA, 1));
        rmaxA = fmaxf(rmaxA, __shfl_xor_sync(0xffffffffu, rmaxA, 2));
        rmaxB = fmaxf(rmaxB, __shfl_xor_sync(0xffffffffu, rmaxB, 1));
        rmaxB = fmaxf(rmaxB, __shfl_xor_sync(0xffffffffu, rmaxB, 2));

        float mnA = fmaxf(mA, rmaxA), mnB = fmaxf(mB, rmaxB);
        float aA = ex2(mA - mnA), aB = ex2(mB - mnB);
        mA = mnA; mB = mnB;

        u32 ph[4][4];
        float sA = 0.f, sB = 0.f;
        #pragma unroll
        for (int kk = 0; kk < 4; kk++) {
            float p0 = ex2(sacc[2 * kk][0] - mnA);
            float p1 = ex2(sacc[2 * kk][1] - mnA);
            float p2 = ex2(sacc[2 * kk][2] - mnB);
            float p3 = ex2(sacc[2 * kk][3] - mnB);
            float p4 = ex2(sacc[2 * kk + 1][0] - mnA);
            float p5 = ex2(sacc[2 * kk + 1][1] - mnA);
            float p6 = ex2(sacc[2 * kk + 1][2] - mnB);
            float p7 = ex2(sacc[2 * kk + 1][3] - mnB);
            sA += (p0 + p1) + (p4 + p5);
            sB += (p2 + p3) + (p6 + p7);
            ph[kk][0] = pack2(p0, p1);
            ph[kk][1] = pack2(p2, p3);
            ph[kk][2] = pack2(p4, p5);
            ph[kk][3] = pack2(p6, p7);
        }
        // lane-partial l; quad reduction deferred to epilogue (alpha quad-uniform)
        lA = fmaf(lA, aA, sA);
        lB = fmaf(lB, aB, sB);

        #pragma unroll
        for (int f = 0; f < 16; f++) {
            oacc[f][0] *= aA; oacc[f][1] *= aA;
            oacc[f][2] *= aB; oacc[f][3] *= aB;
        }

        // ---- O += Ph @ Vh ----
        #pragma unroll
        for (int kk = 0; kk < 4; kk++) {
            #pragma unroll
            for (int dp = 0; dp < 8; dp++) {
                u32 voff = swoff(kk * 16 + vkey, dp * 2 + vchh);
                u32 vb0, vb1, vb2, vb3;
                ldm4t(vhb + voff, vb0, vb1, vb2, vb3);
                mma(oacc[2 * dp],     ph[kk][0], ph[kk][1], ph[kk][2], ph[kk][3], vb0, vb1);
                mma(oacc[2 * dp + 1], ph[kk][0], ph[kk][1], ph[kk][2], ph[kk][3], vb2, vb3);
            }
        }

        CP_WAIT0();
        __syncthreads();
    }

    // ---- epilogue: final l reduction over the quad, then store ----
    lA += __shfl_xor_sync(0xffffffffu, lA, 1);
    lA += __shfl_xor_sync(0xffffffffu, lA, 2);
    lB += __shfl_xor_sync(0xffffffffu, lB, 1);
    lB += __shfl_xor_sync(0xffffffffu, lB, 2);
    const float iA = 1.f / lA, iB = 1.f / lB;
    const int ra = wr0 + (lane >> 2);
    const int rb = ra + 8;
    const int cb = 2 * (lane & 3);
    #pragma unroll
    for (int f = 0; f < 16; f++) {
        float2 va; va.x = oacc[f][0] * iA; va.y = oacc[f][1] * iA;
        float2 vb; vb.x = oacc[f][2] * iB; vb.y = oacc[f][3] * iB;
        *(float2*)(Og + (size_t)ra * Dh + f * 8 + cb) = va;
        *(float2*)(Og + (size_t)rb * Dh + f * 8 + cb) = vb;
    }
}

extern "C" void kernel_launch(void* const* d_in, const int* in_sizes, int n_in,
                              void* d_out, int out_size)
{
    const float* q     = (const float*)d_in[0];
    const float* k     = (const float*)d_in[1];
    const float* v     = (const float*)d_in[2];
    const float* scale = (const float*)d_in[3];
    float* out = (float*)d_out;

    dim3 pg(32, NBH);
    prep_kernel<<<pg, NT>>>(q, k, v, scale);

    cudaFuncSetAttribute(attn_hmma, cudaFuncAttributeMaxDynamicSharedMemorySize, SMEM_BYTES);
    dim3 grid(SEQ / BM, NBH);
    attn_hmma<<<grid, NT, SMEM_BYTES>>>(out);
}

// round 10
// speedup vs baseline: 1.3821x; 1.0251x over previous
#include <cuda_runtime.h>
#include <cuda_fp16.h>

typedef unsigned int u32;

#define NT  256
#define BM  128
#define BN  64
#define Dh  128
#define SEQ 2048
#define NIT (SEQ / BN)
#define NBH 64
#define LOG2E 1.44269504088896340736f

// ---- smem byte layout (main kernel) ----
#define QH_OFF 0
#define QL_OFF 32768
#define K_OFF  65536          // + buf*32768 ; lo at +16384
#define V_OFF  131072         // + buf*16384 (hi only)
#define SMEM_BYTES 163840

// ---- global scratch: pre-split f16 K/V images in exact swizzled smem layout ----
__device__ u32 gKsc[NBH * 32 * 8192];    // per (bh,ktile): 16KB hi + 16KB lo
__device__ u32 gVsc[NBH * 32 * 4096];    // per (bh,ktile): 16KB hi

static __device__ __forceinline__ u32 cvta_smem(const void* p) {
    u32 a;
    asm("{ .reg .u64 t; cvta.to.shared.u64 t, %1; cvt.u32.u64 %0, t; }" : "=r"(a) : "l"(p));
    return a;
}
static __device__ __forceinline__ u32 swoff(int row, int ch) {
    return (u32)(row * 256 + ((ch ^ (row & 7)) << 4));
}
static __device__ __forceinline__ float ex2(float x) {
    float y; asm("ex2.approx.f32 %0, %1;" : "=f"(y) : "f"(x)); return y;
}
static __device__ __forceinline__ u32 pack2(float x0, float x1) {
    __half2 h = __floats2half2_rn(x0, x1);
    return *(u32*)&h;
}
static __device__ __forceinline__ void split2(float x0, float x1, u32& hi, u32& lo) {
    __half2 h = __floats2half2_rn(x0, x1);
    float2  b = __half22float2(h);
    __half2 l = __floats2half2_rn(x0 - b.x, x1 - b.y);
    hi = *(u32*)&h; lo = *(u32*)&l;
}

static __device__ __forceinline__ void ldm4(u32 addr, u32& r0, u32& r1, u32& r2, u32& r3) {
    asm volatile("ldmatrix.sync.aligned.m8n8.x4.shared.b16 {%0,%1,%2,%3}, [%4];"
                 : "=r"(r0), "=r"(r1), "=r"(r2), "=r"(r3) : "r"(addr));
}
static __device__ __forceinline__ void ldm4t(u32 addr, u32& r0, u32& r1, u32& r2, u32& r3) {
    asm volatile("ldmatrix.sync.aligned.m8n8.x4.trans.shared.b16 {%0,%1,%2,%3}, [%4];"
                 : "=r"(r0), "=r"(r1), "=r"(r2), "=r"(r3) : "r"(addr));
}
static __device__ __forceinline__ void mma(float* d, u32 a0, u32 a1, u32 a2, u32 a3, u32 b0, u32 b1) {
    asm volatile("mma.sync.aligned.m16n8k16.row.col.f32.f16.f16.f32 "
                 "{%0,%1,%2,%3}, {%4,%5,%6,%7}, {%8,%9}, {%0,%1,%2,%3};"
                 : "+f"(d[0]), "+f"(d[1]), "+f"(d[2]), "+f"(d[3])
                 : "r"(a0), "r"(a1), "r"(a2), "r"(a3), "r"(b0), "r"(b1));
}
#define CP16(dst, src) \
    asm volatile("cp.async.cg.shared.global [%0], [%1], 16;" :: "r"(dst), "l"(src))
#define CP_COMMIT() asm volatile("cp.async.commit_group;" ::: "memory")
#define CP_WAIT0()  asm volatile("cp.async.wait_group 0;"  ::: "memory")

// ============ prep kernel: split K/V f32 -> f16 hi/lo swizzled images ============
__global__ __launch_bounds__(NT, 4)
void prep_kernel(const float* __restrict__ kg, const float* __restrict__ vg)
{
    const int t = blockIdx.x;        // 0..31 (64-row tile)
    const int bh = blockIdx.y;       // 0..63
    const int tid = threadIdx.x;
    const size_t base = (size_t)bh * SEQ * Dh + (size_t)t * 64 * Dh;

    // ---- K tile t: hi + lo ----
    {
        const float* src = kg + base;
        u32* dh = gKsc + (size_t)(bh * 32 + t) * 8192;
        u32* dl = dh + 4096;
        #pragma unroll
        for (int p = 0; p < 4; p++) {
            int idx = tid + p * 256;
            int row = idx >> 4, ch = idx & 15;
            const float* s = src + (size_t)row * Dh + ch * 8;
            float4 a = *(const float4*)s;
            float4 b = *(const float4*)(s + 4);
            u32 h0, l0, h1, l1, h2, l2, h3, l3;
            split2(a.x, a.y, h0, l0); split2(a.z, a.w, h1, l1);
            split2(b.x, b.y, h2, l2); split2(b.z, b.w, h3, l3);
            u32 off = swoff(row, ch) >> 2;
            *(uint4*)(dh + off) = make_uint4(h0, h1, h2, h3);
            *(uint4*)(dl + off) = make_uint4(l0, l1, l2, l3);
        }
    }
    // ---- V tile t: hi only ----
    {
        const float* src = vg + base;
        u32* dv = gVsc + (size_t)(bh * 32 + t) * 4096;
        #pragma unroll
        for (int p = 0; p < 4; p++) {
            int idx = tid + p * 256;
            int row = idx >> 4, ch = idx & 15;
            const float* s = src + (size_t)row * Dh + ch * 8;
            float4 a = *(const float4*)s;
            float4 b = *(const float4*)(s + 4);
            u32 off = swoff(row, ch) >> 2;
            *(uint4*)(dv + off) = make_uint4(pack2(a.x, a.y), pack2(a.z, a.w),
                                             pack2(b.x, b.y), pack2(b.z, b.w));
        }
    }
}

// ============ main kernel ============
__global__ __launch_bounds__(NT, 1)
void attn_hmma(const float* __restrict__ qg, const float* __restrict__ scg,
               float* __restrict__ og)
{
    extern __shared__ char sm[];
    const u32 smb = cvta_smem(sm);
    const int tid = threadIdx.x, lane = tid & 31, wid = tid >> 5;

    const int tile = blockIdx.x;
    const int bh   = blockIdx.y;
    const float* Qg = qg + (size_t)bh * SEQ * Dh + (size_t)tile * BM * Dh;
    float*       Og = og + (size_t)bh * SEQ * Dh + (size_t)tile * BM * Dh;
    const float scL = scg[bh] * LOG2E;

    const char* gK = (const char*)(gKsc + (size_t)(bh * 32) * 8192);
    const char* gV = (const char*)(gVsc + (size_t)(bh * 32) * 4096);

    // ---- prologue: async copy K/V tile 0, convert Q (scale folded) in parallel ----
    #pragma unroll
    for (int i = 0; i < 8; i++)
        CP16(smb + K_OFF + tid * 16 + i * 4096, gK + tid * 16 + i * 4096);
    #pragma unroll
    for (int i = 0; i < 4; i++)
        CP16(smb + V_OFF + tid * 16 + i * 4096, gV + tid * 16 + i * 4096);
    CP_COMMIT();

    #pragma unroll
    for (int p = 0; p < 8; p++) {
        int idx = tid + p * 256;
        int row = idx >> 4, ch = idx & 15;
        const float* s = Qg + (size_t)row * Dh + ch * 8;
        float4 a = *(const float4*)s;
        float4 b = *(const float4*)(s + 4);
        u32 h0, l0, h1, l1, h2, l2, h3, l3;
        split2(a.x * scL, a.y * scL, h0, l0); split2(a.z * scL, a.w * scL, h1, l1);
        split2(b.x * scL, b.y * scL, h2, l2); split2(b.z * scL, b.w * scL, h3, l3);
        u32 off = swoff(row, ch);
        *(uint4*)(sm + QH_OFF + off) = make_uint4(h0, h1, h2, h3);
        *(uint4*)(sm + QL_OFF + off) = make_uint4(l0, l1, l2, l3);
    }
    CP_WAIT0();
    __syncthreads();

    // ---- per-warp state ----
    float oacc[16][4];
    #pragma unroll
    for (int f = 0; f < 16; f++)
        #pragma unroll
        for (int j = 0; j < 4; j++) oacc[f][j] = 0.f;
    float mA = -1e30f, mB = -1e30f, lA = 0.f, lB = 0.f;   // l: lane-partial

    const int wr0 = wid * 16;
    const int qrow = wr0 + (lane & 15);
    const int qchh = lane >> 4;
    const int kn   = (lane & 7) + ((lane >> 4) << 3);
    const int kchh = (lane >> 3) & 1;
    const int vkey = (lane & 7) + (((lane >> 3) & 1) << 3);
    const int vchh = lane >> 4;

    #pragma unroll 1
    for (int n = 0; n < NIT; n++) {
        const int buf = n & 1;
        const u32 khb = smb + K_OFF + buf * 32768;
        const u32 klb = khb + 16384;
        const u32 vhb = smb + V_OFF + buf * 16384;

        // ---- issue async copies for tile n+1 ----
        if (n + 1 < NIT) {
            const char* nk = gK + (size_t)(n + 1) * 32768;
            const char* nv = gV + (size_t)(n + 1) * 16384;
            u32 kd = smb + K_OFF + (buf ^ 1) * 32768 + tid * 16;
            u32 vd = smb + V_OFF + (buf ^ 1) * 16384 + tid * 16;
            #pragma unroll
            for (int i = 0; i < 8; i++)
                CP16(kd + i * 4096, nk + tid * 16 + i * 4096);
            #pragma unroll
            for (int i = 0; i < 4; i++)
                CP16(vd + i * 4096, nv + tid * 16 + i * 4096);
            CP_COMMIT();
        }

        // ---- S = (Qh+Ql)(Kh+Kl)^T, 3 products ----
        float sacc[8][4];
        #pragma unroll
        for (int f = 0; f < 8; f++)
            #pragma unroll
            for (int j = 0; j < 4; j++) sacc[f][j] = 0.f;

        #pragma unroll
        for (int kk = 0; kk < 8; kk++) {
            u32 qoff = swoff(qrow, kk * 2 + qchh);
            u32 qh0, qh1, qh2, qh3, ql0, ql1, ql2, ql3;
            ldm4(smb + QH_OFF + qoff, qh0, qh1, qh2, qh3);
            ldm4(smb + QL_OFF + qoff, ql0, ql1, ql2, ql3);
            #pragma unroll
            for (int jp = 0; jp < 4; jp++) {
                u32 koff = swoff(jp * 16 + kn, kk * 2 + kchh);
                u32 kb0, kb1, kb2, kb3, lb0, lb1, lb2, lb3;
                ldm4(khb + koff, kb0, kb1, kb2, kb3);
                ldm4(klb + koff, lb0, lb1, lb2, lb3);
                mma(sacc[jp * 2],     qh0, qh1, qh2, qh3, kb0, kb1);
                mma(sacc[jp * 2],     qh0, qh1, qh2, qh3, lb0, lb1);
                mma(sacc[jp * 2],     ql0, ql1, ql2, ql3, kb0, kb1);
                mma(sacc[jp * 2 + 1], qh0, qh1, qh2, qh3, kb2, kb3);
                mma(sacc[jp * 2 + 1], qh0, qh1, qh2, qh3, lb2, lb3);
                mma(sacc[jp * 2 + 1], ql0, ql1, ql2, ql3, kb2, kb3);
            }
        }

        // ---- phase 1: max scan, alpha, O-rescale (no MUFU in chain) ----
        float rmaxA = -1e30f, rmaxB = -1e30f;
        #pragma unroll
        for (int f = 0; f < 8; f++) {
            rmaxA = fmaxf(rmaxA, fmaxf(sacc[f][0], sacc[f][1]));
            rmaxB = fmaxf(rmaxB, fmaxf(sacc[f][2], sacc[f][3]));
        }
        rmaxA = fmaxf(rmaxA, __shfl_xor_sync(0xffffffffu, rmaxA, 1));
        rmaxA = fmaxf(rmaxA, __shfl_xor_sync(0xffffffffu, rmaxA, 2));
        rmaxB = fmaxf(rmaxB, __shfl_xor_sync(0xffffffffu, rmaxB, 1));
        rmaxB = fmaxf(rmaxB, __shfl_xor_sync(0xffffffffu, rmaxB, 2));

        float mnA = fmaxf(mA, rmaxA), mnB = fmaxf(mB, rmaxB);
        float aA = ex2(mA - mnA), aB = ex2(mB - mnB);
        mA = mnA; mB = mnB;

        #pragma unroll
        for (int f = 0; f < 16; f++) {
            oacc[f][0] *= aA; oacc[f][1] *= aA;
            oacc[f][2] *= aB; oacc[f][3] *= aB;
        }

        // ---- phase 2: chunked softmax + PV interleave (MUFU hides under MMA) ----
        float sA = 0.f, sB = 0.f;
        #pragma unroll
        for (int kk = 0; kk < 4; kk++) {
            float p0 = ex2(sacc[2 * kk][0] - mnA);
            float p1 = ex2(sacc[2 * kk][1] - mnA);
            float p2 = ex2(sacc[2 * kk][2] - mnB);
            float p3 = ex2(sacc[2 * kk][3] - mnB);
            float p4 = ex2(sacc[2 * kk + 1][0] - mnA);
            float p5 = ex2(sacc[2 * kk + 1][1] - mnA);
            float p6 = ex2(sacc[2 * kk + 1][2] - mnB);
            float p7 = ex2(sacc[2 * kk + 1][3] - mnB);
            sA += (p0 + p1) + (p4 + p5);
            sB += (p2 + p3) + (p6 + p7);
            u32 ph0 = pack2(p0, p1);
            u32 ph1 = pack2(p2, p3);
            u32 ph2 = pack2(p4, p5);
            u32 ph3 = pack2(p6, p7);
            #pragma unroll
            for (int dp = 0; dp < 8; dp++) {
                u32 voff = swoff(kk * 16 + vkey, dp * 2 + vchh);
                u32 vb0, vb1, vb2, vb3;
                ldm4t(vhb + voff, vb0, vb1, vb2, vb3);
                mma(oacc[2 * dp],     ph0, ph1, ph2, ph3, vb0, vb1);
                mma(oacc[2 * dp + 1], ph0, ph1, ph2, ph3, vb2, vb3);
            }
        }
        // lane-partial l; quad reduction deferred to epilogue (alpha quad-uniform)
        lA = fmaf(lA, aA, sA);
        lB = fmaf(lB, aB, sB);

        CP_WAIT0();
        __syncthreads();
    }

    // ---- epilogue: final l reduction over the quad, then store ----
    lA += __shfl_xor_sync(0xffffffffu, lA, 1);
    lA += __shfl_xor_sync(0xffffffffu, lA, 2);
    lB += __shfl_xor_sync(0xffffffffu, lB, 1);
    lB += __shfl_xor_sync(0xffffffffu, lB, 2);
    const float iA = 1.f / lA, iB = 1.f / lB;
    const int ra = wr0 + (lane >> 2);
    const int rb = ra + 8;
    const int cb = 2 * (lane & 3);
    #pragma unroll
    for (int f = 0; f < 16; f++) {
        float2 va; va.x = oacc[f][0] * iA; va.y = oacc[f][1] * iA;
        float2 vb; vb.x = oacc[f][2] * iB; vb.y = oacc[f][3] * iB;
        *(float2*)(Og + (size_t)ra * Dh + f * 8 + cb) = va;
        *(float2*)(Og + (size_t)rb * Dh + f * 8 + cb) = vb;
    }
}

extern "C" void kernel_launch(void* const* d_in, const int* in_sizes, int n_in,
                              void* d_out, int out_size)
{
    const float* q     = (const float*)d_in[0];
    const float* k     = (const float*)d_in[1];
    const float* v     = (const float*)d_in[2];
    const float* scale = (const float*)d_in[3];
    float* out = (float*)d_out;

    dim3 pg(32, NBH);
    prep_kernel<<<pg, NT>>>(k, v);

    cudaFuncSetAttribute(attn_hmma, cudaFuncAttributeMaxDynamicSharedMemorySize, SMEM_BYTES);
    dim3 grid(SEQ / BM, NBH);
    attn_hmma<<<grid, NT, SMEM_BYTES>>>(q, scale, out);
}

// round 12
// speedup vs baseline: 1.4693x; 1.0631x over previous
#include <cuda_runtime.h>
#include <cuda_fp16.h>

typedef unsigned int u32;

#define NT  256
#define BM  128
#define BN  64
#define Dh  128
#define SEQ 2048
#define NIT (SEQ / BN)
#define NBH 64
#define LOG2E 1.44269504088896340736f

// ---- smem byte layout (main kernel) ----
#define QH_OFF 0
#define QL_OFF 32768
#define K_OFF  65536            // 3 bufs x 32768 (hi 16K + lo 16K)
#define V_OFF  163840           // 3 bufs x 16384 (hi only)
#define MB_OFF 212992           // 3 mbarriers x 8B
#define SMEM_BYTES 213248

// ---- global scratch: pre-split f16 K/V images in exact swizzled smem layout ----
__device__ u32 gKsc[NBH * 32 * 8192];    // per (bh,ktile): 16KB hi + 16KB lo
__device__ u32 gVsc[NBH * 32 * 4096];    // per (bh,ktile): 16KB hi

static __device__ __forceinline__ u32 cvta_smem(const void* p) {
    u32 a;
    asm("{ .reg .u64 t; cvta.to.shared.u64 t, %1; cvt.u32.u64 %0, t; }" : "=r"(a) : "l"(p));
    return a;
}
static __device__ __forceinline__ u32 swoff(int row, int ch) {
    return (u32)(row * 256 + ((ch ^ (row & 7)) << 4));
}
static __device__ __forceinline__ float ex2(float x) {
    float y; asm("ex2.approx.f32 %0, %1;" : "=f"(y) : "f"(x)); return y;
}
static __device__ __forceinline__ u32 pack2(float x0, float x1) {
    __half2 h = __floats2half2_rn(x0, x1);
    return *(u32*)&h;
}
static __device__ __forceinline__ void split2(float x0, float x1, u32& hi, u32& lo) {
    __half2 h = __floats2half2_rn(x0, x1);
    float2  b = __half22float2(h);
    __half2 l = __floats2half2_rn(x0 - b.x, x1 - b.y);
    hi = *(u32*)&h; lo = *(u32*)&l;
}

static __device__ __forceinline__ void ldm4(u32 addr, u32& r0, u32& r1, u32& r2, u32& r3) {
    asm volatile("ldmatrix.sync.aligned.m8n8.x4.shared.b16 {%0,%1,%2,%3}, [%4];"
                 : "=r"(r0), "=r"(r1), "=r"(r2), "=r"(r3) : "r"(addr));
}
static __device__ __forceinline__ void ldm4t(u32 addr, u32& r0, u32& r1, u32& r2, u32& r3) {
    asm volatile("ldmatrix.sync.aligned.m8n8.x4.trans.shared.b16 {%0,%1,%2,%3}, [%4];"
                 : "=r"(r0), "=r"(r1), "=r"(r2), "=r"(r3) : "r"(addr));
}
static __device__ __forceinline__ void mma(float* d, u32 a0, u32 a1, u32 a2, u32 a3, u32 b0, u32 b1) {
    asm volatile("mma.sync.aligned.m16n8k16.row.col.f32.f16.f16.f32 "
                 "{%0,%1,%2,%3}, {%4,%5,%6,%7}, {%8,%9}, {%0,%1,%2,%3};"
                 : "+f"(d[0]), "+f"(d[1]), "+f"(d[2]), "+f"(d[3])
                 : "r"(a0), "r"(a1), "r"(a2), "r"(a3), "r"(b0), "r"(b1));
}
#define CP16(dst, src) \
    asm volatile("cp.async.cg.shared.global [%0], [%1], 16;" :: "r"(dst), "l"(src))
// .noinc is load-bearing: the default form increments the pending count before
// arriving (net zero); with init count = NT and one arrive per thread we must
// NOT increment, otherwise the phase never completes (round-11 deadlock).
#define CP_MBAR_ARRIVE(mb) \
    asm volatile("cp.async.mbarrier.arrive.noinc.shared.b64 [%0];" :: "r"(mb) : "memory")
#define MBAR_INIT(mb, c) \
    asm volatile("mbarrier.init.shared.b64 [%0], %1;" :: "r"(mb), "r"(c) : "memory")
#define MBAR_WAIT(mb, par) do { \
    u32 _done = 0; \
    while (!_done) { \
        asm volatile("{\n\t.reg .pred p;\n\t" \
            "mbarrier.test_wait.parity.shared.b64 p, [%1], %2;\n\t" \
            "selp.u32 %0, 1, 0, p;\n\t}" \
            : "=r"(_done) : "r"(mb), "r"((u32)(par)) : "memory"); \
    } \
} while (0)

// ============ prep kernel: split K/V f32 -> f16 hi/lo swizzled images ============
__global__ __launch_bounds__(NT, 4)
void prep_kernel(const float* __restrict__ kg, const float* __restrict__ vg)
{
    const int t = blockIdx.x;        // 0..31 (64-row tile)
    const int bh = blockIdx.y;       // 0..63
    const int tid = threadIdx.x;
    const size_t base = (size_t)bh * SEQ * Dh + (size_t)t * 64 * Dh;

    {
        const float* src = kg + base;
        u32* dh = gKsc + (size_t)(bh * 32 + t) * 8192;
        u32* dl = dh + 4096;
        #pragma unroll
        for (int p = 0; p < 4; p++) {
            int idx = tid + p * 256;
            int row = idx >> 4, ch = idx & 15;
            const float* s = src + (size_t)row * Dh + ch * 8;
            float4 a = *(const float4*)s;
            float4 b = *(const float4*)(s + 4);
            u32 h0, l0, h1, l1, h2, l2, h3, l3;
            split2(a.x, a.y, h0, l0); split2(a.z, a.w, h1, l1);
            split2(b.x, b.y, h2, l2); split2(b.z, b.w, h3, l3);
            u32 off = swoff(row, ch) >> 2;
            *(uint4*)(dh + off) = make_uint4(h0, h1, h2, h3);
            *(uint4*)(dl + off) = make_uint4(l0, l1, l2, l3);
        }
    }
    {
        const float* src = vg + base;
        u32* dv = gVsc + (size_t)(bh * 32 + t) * 4096;
        #pragma unroll
        for (int p = 0; p < 4; p++) {
            int idx = tid + p * 256;
            int row = idx >> 4, ch = idx & 15;
            const float* s = src + (size_t)row * Dh + ch * 8;
            float4 a = *(const float4*)s;
            float4 b = *(const float4*)(s + 4);
            u32 off = swoff(row, ch) >> 2;
            *(uint4*)(dv + off) = make_uint4(pack2(a.x, a.y), pack2(a.z, a.w),
                                             pack2(b.x, b.y), pack2(b.z, b.w));
        }
    }
}

// ============ main kernel ============
__global__ __launch_bounds__(NT, 1)
void attn_hmma(const float* __restrict__ qg, const float* __restrict__ scg,
               float* __restrict__ og)
{
    extern __shared__ char sm[];
    const u32 smb = cvta_smem(sm);
    const int tid = threadIdx.x, lane = tid & 31, wid = tid >> 5;

    const int tile = blockIdx.x;
    const int bh   = blockIdx.y;
    const float* Qg = qg + (size_t)bh * SEQ * Dh + (size_t)tile * BM * Dh;
    float*       Og = og + (size_t)bh * SEQ * Dh + (size_t)tile * BM * Dh;
    const float scL = scg[bh] * LOG2E;

    const char* gK = (const char*)(gKsc + (size_t)(bh * 32) * 8192);
    const char* gV = (const char*)(gVsc + (size_t)(bh * 32) * 4096);

    // per-thread copy of tile t into buf b3, then arrive on its mbarrier
    auto issue_tile = [&](int t, int b3) {
        const char* nk = gK + (size_t)t * 32768;
        const char* nv = gV + (size_t)t * 16384;
        u32 kd = smb + K_OFF + b3 * 32768 + tid * 16;
        u32 vd = smb + V_OFF + b3 * 16384 + tid * 16;
        #pragma unroll
        for (int i = 0; i < 8; i++)
            CP16(kd + i * 4096, nk + tid * 16 + i * 4096);
        #pragma unroll
        for (int i = 0; i < 4; i++)
            CP16(vd + i * 4096, nv + tid * 16 + i * 4096);
        CP_MBAR_ARRIVE(smb + MB_OFF + b3 * 8);
    };

    // ---- prologue ----
    if (tid == 0) {
        MBAR_INIT(smb + MB_OFF + 0, NT);
        MBAR_INIT(smb + MB_OFF + 8, NT);
        MBAR_INIT(smb + MB_OFF + 16, NT);
    }
    __syncthreads();

    issue_tile(0, 0);

    // convert Q (scale folded, split) while tile-0 copies fly
    #pragma unroll
    for (int p = 0; p < 8; p++) {
        int idx = tid + p * 256;
        int row = idx >> 4, ch = idx & 15;
        const float* s = Qg + (size_t)row * Dh + ch * 8;
        float4 a = *(const float4*)s;
        float4 b = *(const float4*)(s + 4);
        u32 h0, l0, h1, l1, h2, l2, h3, l3;
        split2(a.x * scL, a.y * scL, h0, l0); split2(a.z * scL, a.w * scL, h1, l1);
        split2(b.x * scL, b.y * scL, h2, l2); split2(b.z * scL, b.w * scL, h3, l3);
        u32 off = swoff(row, ch);
        *(uint4*)(sm + QH_OFF + off) = make_uint4(h0, h1, h2, h3);
        *(uint4*)(sm + QL_OFF + off) = make_uint4(l0, l1, l2, l3);
    }
    __syncthreads();   // Q visible to all warps

    // ---- per-warp state ----
    float oacc[16][4];
    #pragma unroll
    for (int f = 0; f < 16; f++)
        #pragma unroll
        for (int j = 0; j < 4; j++) oacc[f][j] = 0.f;
    float mA = -1e30f, mB = -1e30f, lA = 0.f, lB = 0.f;   // l: lane-partial

    const int wr0 = wid * 16;
    const int qrow = wr0 + (lane & 15);
    const int qchh = lane >> 4;
    const int kn   = (lane & 7) + ((lane >> 4) << 3);
    const int kchh = (lane >> 3) & 1;
    const int vkey = (lane & 7) + (((lane >> 3) & 1) << 3);
    const int vchh = lane >> 4;

    int b3 = 0, par = 0;   // tile n: buf b3 = n%3, parity = (n/3)&1

    #pragma unroll 1
    for (int n = 0; n < NIT; n++) {
        // wait for tile n's copies (all threads' slices) to land
        MBAR_WAIT(smb + MB_OFF + b3 * 8, par);

        // issue copies for tile n+1 (safe: all threads have finished iter n-2,
        // so buf (n+1)%3's previous readers are done)
        const int b3n = (b3 == 2) ? 0 : b3 + 1;
        if (n + 1 < NIT) issue_tile(n + 1, b3n);

        const u32 khb = smb + K_OFF + b3 * 32768;
        const u32 klb = khb + 16384;
        const u32 vhb = smb + V_OFF + b3 * 16384;

        // ---- S = (Qh+Ql)(Kh+Kl)^T, 3 products ----
        float sacc[8][4];
        #pragma unroll
        for (int f = 0; f < 8; f++)
            #pragma unroll
            for (int j = 0; j < 4; j++) sacc[f][j] = 0.f;

        #pragma unroll
        for (int kk = 0; kk < 8; kk++) {
            u32 qoff = swoff(qrow, kk * 2 + qchh);
            u32 qh0, qh1, qh2, qh3, ql0, ql1, ql2, ql3;
            ldm4(smb + QH_OFF + qoff, qh0, qh1, qh2, qh3);
            ldm4(smb + QL_OFF + qoff, ql0, ql1, ql2, ql3);
            #pragma unroll
            for (int jp = 0; jp < 4; jp++) {
                u32 koff = swoff(jp * 16 + kn, kk * 2 + kchh);
                u32 kb0, kb1, kb2, kb3, lb0, lb1, lb2, lb3;
                ldm4(khb + koff, kb0, kb1, kb2, kb3);
                ldm4(klb + koff, lb0, lb1, lb2, lb3);
                mma(sacc[jp * 2],     qh0, qh1, qh2, qh3, kb0, kb1);
                mma(sacc[jp * 2],     qh0, qh1, qh2, qh3, lb0, lb1);
                mma(sacc[jp * 2],     ql0, ql1, ql2, ql3, kb0, kb1);
                mma(sacc[jp * 2 + 1], qh0, qh1, qh2, qh3, kb2, kb3);
                mma(sacc[jp * 2 + 1], qh0, qh1, qh2, qh3, lb2, lb3);
                mma(sacc[jp * 2 + 1], ql0, ql1, ql2, ql3, kb2, kb3);
            }
        }

        // ---- phase 1: max scan, alpha, O-rescale ----
        float rmaxA = -1e30f, rmaxB = -1e30f;
        #pragma unroll
        for (int f = 0; f < 8; f++) {
            rmaxA = fmaxf(rmaxA, fmaxf(sacc[f][0], sacc[f][1]));
            rmaxB = fmaxf(rmaxB, fmaxf(sacc[f][2], sacc[f][3]));
        }
        rmaxA = fmaxf(rmaxA, __shfl_xor_sync(0xffffffffu, rmaxA, 1));
        rmaxA = fmaxf(rmaxA, __shfl_xor_sync(0xffffffffu, rmaxA, 2));
        rmaxB = fmaxf(rmaxB, __shfl_xor_sync(0xffffffffu, rmaxB, 1));
        rmaxB = fmaxf(rmaxB, __shfl_xor_sync(0xffffffffu, rmaxB, 2));

        float mnA = fmaxf(mA, rmaxA), mnB = fmaxf(mB, rmaxB);
        float aA = ex2(mA - mnA), aB = ex2(mB - mnB);
        mA = mnA; mB = mnB;

        #pragma unroll
        for (int f = 0; f < 16; f++) {
            oacc[f][0] *= aA; oacc[f][1] *= aA;
            oacc[f][2] *= aB; oacc[f][3] *= aB;
        }

        // ---- phase 2: chunked softmax + PV interleave ----
        float sA = 0.f, sB = 0.f;
        #pragma unroll
        for (int kk = 0; kk < 4; kk++) {
            float p0 = ex2(sacc[2 * kk][0] - mnA);
            float p1 = ex2(sacc[2 * kk][1] - mnA);
            float p2 = ex2(sacc[2 * kk][2] - mnB);
            float p3 = ex2(sacc[2 * kk][3] - mnB);
            float p4 = ex2(sacc[2 * kk + 1][0] - mnA);
            float p5 = ex2(sacc[2 * kk + 1][1] - mnA);
            float p6 = ex2(sacc[2 * kk + 1][2] - mnB);
            float p7 = ex2(sacc[2 * kk + 1][3] - mnB);
            sA += (p0 + p1) + (p4 + p5);
            sB += (p2 + p3) + (p6 + p7);
            u32 ph0 = pack2(p0, p1);
            u32 ph1 = pack2(p2, p3);
            u32 ph2 = pack2(p4, p5);
            u32 ph3 = pack2(p6, p7);
            #pragma unroll
            for (int dp = 0; dp < 8; dp++) {
                u32 voff = swoff(kk * 16 + vkey, dp * 2 + vchh);
                u32 vb0, vb1, vb2, vb3;
                ldm4t(vhb + voff, vb0, vb1, vb2, vb3);
                mma(oacc[2 * dp],     ph0, ph1, ph2, ph3, vb0, vb1);
                mma(oacc[2 * dp + 1], ph0, ph1, ph2, ph3, vb2, vb3);
            }
        }
        lA = fmaf(lA, aA, sA);
        lB = fmaf(lB, aB, sB);

        // advance ring
        if (++b3 == 3) { b3 = 0; par ^= 1; }
    }

    // ---- epilogue: final l reduction over the quad, then store ----
    lA += __shfl_xor_sync(0xffffffffu, lA, 1);
    lA += __shfl_xor_sync(0xffffffffu, lA, 2);
    lB += __shfl_xor_sync(0xffffffffu, lB, 1);
    lB += __shfl_xor_sync(0xffffffffu, lB, 2);
    const float iA = 1.f / lA, iB = 1.f / lB;
    const int ra = wr0 + (lane >> 2);
    const int rb = ra + 8;
    const int cb = 2 * (lane & 3);
    #pragma unroll
    for (int f = 0; f < 16; f++) {
        float2 va; va.x = oacc[f][0] * iA; va.y = oacc[f][1] * iA;
        float2 vb; vb.x = oacc[f][2] * iB; vb.y = oacc[f][3] * iB;
        *(float2*)(Og + (size_t)ra * Dh + f * 8 + cb) = va;
        *(float2*)(Og + (size_t)rb * Dh + f * 8 + cb) = vb;
    }
}

extern "C" void kernel_launch(void* const* d_in, const int* in_sizes, int n_in,
                              void* d_out, int out_size)
{
    const float* q     = (const float*)d_in[0];
    const float* k     = (const float*)d_in[1];
    const float* v     = (const float*)d_in[2];
    const float* scale = (const float*)d_in[3];
    float* out = (float*)d_out;

    dim3 pg(32, NBH);
    prep_kernel<<<pg, NT>>>(k, v);

    cudaFuncSetAttribute(attn_hmma, cudaFuncAttributeMaxDynamicSharedMemorySize, SMEM_BYTES);
    dim3 grid(SEQ / BM, NBH);
    attn_hmma<<<grid, NT, SMEM_BYTES>>>(q, scale, out);
}